// round 15
// baseline (speedup 1.0000x reference)
#include <cuda_runtime.h>
#include <cuda_fp16.h>
#include <cstdint>

#define E_MAX 100096
#define IN_F  256
#define HID   128

// scratch (device globals = allowed scratch)
__device__ __half g_th[(size_t)E_MAX * HID];    // fp16 t (self + gather)
__device__ __half g_wh[HID * IN_F];             // W transposed [n][k], fp16

__device__ __forceinline__ uint32_t smem_u32(const void* p) {
    uint32_t a;
    asm("{ .reg .u64 t; cvta.to.shared.u64 t, %1; cvt.u32.u64 %0, t; }" : "=r"(a) : "l"(p));
    return a;
}
__device__ __forceinline__ void ldsm_x4(uint32_t& r0, uint32_t& r1, uint32_t& r2,
                                        uint32_t& r3, uint32_t addr) {
    asm volatile("ldmatrix.sync.aligned.m8n8.x4.shared.b16 {%0,%1,%2,%3}, [%4];"
                 : "=r"(r0), "=r"(r1), "=r"(r2), "=r"(r3) : "r"(addr));
}
__device__ __forceinline__ void mma16816(float* c, uint32_t a0, uint32_t a1,
                                         uint32_t a2, uint32_t a3,
                                         uint32_t b0, uint32_t b1) {
    asm volatile(
        "mma.sync.aligned.m16n8k16.row.col.f32.f16.f16.f32 "
        "{%0,%1,%2,%3}, {%4,%5,%6,%7}, {%8,%9}, {%0,%1,%2,%3};"
        : "+f"(c[0]), "+f"(c[1]), "+f"(c[2]), "+f"(c[3])
        : "r"(a0), "r"(a1), "r"(a2), "r"(a3), "r"(b0), "r"(b1));
}
__device__ __forceinline__ void cp_async16(uint32_t dst, const void* src) {
    asm volatile("cp.async.cg.shared.global [%0], [%1], 16;" :: "r"(dst), "l"(src));
}
#define CP_COMMIT() asm volatile("cp.async.commit_group;" ::: "memory")
#define CP_WAIT0()  asm volatile("cp.async.wait_group 0;" ::: "memory")

// =====================================================================
// W transpose -> fp16 (one-shot tiny kernel)
// =====================================================================
__global__ void wconv_kernel(const float* __restrict__ W) {
    int i = blockIdx.x * 256 + threadIdx.x;
    if (i >= IN_F * HID) return;
    int k = i >> 7, n = i & 127;
    g_wh[n * IN_F + k] = __float2half_rn(W[i]);
}

// =====================================================================
// t = Xh @ Wh + b : single-pass fp16 HMMA, fp32 accum.
// CTA = 64 rows x 128 cols, 8 warps (2m x 4n), warp tile 32x32, BK=32.
// 41KB smem + 32 acc regs -> 3 CTAs/SM (was 2), smoother waves.
// =====================================================================
#define BK 32
#define STR 40                       // smem row stride (halves): 80 B
#define TILE_B (128 * STR * 2)       // 10240 B per fp16 B tile

#define SM_XF 0                      // X fp32 staging: 2 x 8192
#define SM_AH 16384                  // A fp16 tile [64][STR] = 5120
#define SM_B  21504                  // B tiles: 2 x 10240 (multiple of 128)
#define SMEM_BYTES (21504 + 20480)   // 41984

__device__ __forceinline__ void prefetch_chunk(
    uint32_t smb, int buf,
    const float4* __restrict__ X4,
    const uint4* __restrict__ bh4,
    int tid, int rowBase, int kc, int E)
{
    uint32_t xdst = smb + SM_XF + buf * 8192;
#pragma unroll
    for (int it = 0; it < 2; ++it) {
        int i = it * 256 + tid;          // 512 float4 (64 rows x 8 f4)
        int r = i >> 3, f = i & 7;
        int grow = rowBase + r;
        if (grow >= E) grow = E - 1;
        cp_async16(xdst + i * 16, X4 + grow * (IN_F / 4) + kc * 8 + f);
    }
    uint32_t bdst = smb + SM_B + buf * TILE_B;
#pragma unroll
    for (int it = 0; it < 2; ++it) {
        int i = it * 256 + tid;          // 512 uint4 (128 n x 4 u4)
        int n = i >> 2, q = i & 3;
        uint32_t off = (uint32_t)(n * STR + q * 8) * 2;    // 16B-aligned
        cp_async16(bdst + off, bh4 + n * 32 + kc * 4 + q);
    }
    CP_COMMIT();
}

__device__ __forceinline__ void convert_A(char* smem, int buf, int tid) {
    const float4* xf = (const float4*)(smem + SM_XF + buf * 8192);
    __half* sAh = (__half*)(smem + SM_AH);
#pragma unroll
    for (int it = 0; it < 2; ++it) {
        int i = it * 256 + tid;          // 512 float4
        int r = i >> 3, f = i & 7;
        float4 v = xf[i];
        uint2 hp;
        hp.x = ((uint32_t)__half_as_ushort(__float2half_rn(v.y)) << 16)
             |  __half_as_ushort(__float2half_rn(v.x));
        hp.y = ((uint32_t)__half_as_ushort(__float2half_rn(v.w)) << 16)
             |  __half_as_ushort(__float2half_rn(v.z));
        *(uint2*)(sAh + r * STR + f * 4) = hp;
    }
}

__global__ __launch_bounds__(256, 3)
void gemm_mma_kernel(const float* __restrict__ X,
                     const float* __restrict__ bias,
                     int E) {
    extern __shared__ char smem[];

    const int tid  = threadIdx.x;
    const int wid  = tid >> 5;
    const int lane = tid & 31;
    const int wm   = wid & 1;        // 2 warp-rows of 32
    const int wn   = wid >> 1;       // 4 warp-cols of 32
    const int rowBase = blockIdx.x * 64;

    float acc[2][4][4];
#pragma unroll
    for (int mi = 0; mi < 2; ++mi)
#pragma unroll
        for (int ni = 0; ni < 4; ++ni)
#pragma unroll
            for (int q = 0; q < 4; ++q) acc[mi][ni][q] = 0.f;

    const float4* X4  = (const float4*)X;
    const uint4*  bh4 = (const uint4*)g_wh;

    const uint32_t smb = smem_u32(smem);

    const int lrow = (lane & 7) + ((lane >> 3) & 1) * 8;
    const int lkof = ((lane >> 4) & 1) * 8;

    prefetch_chunk(smb, 0, X4, bh4, tid, rowBase, 0, E);

    for (int kc = 0; kc < IN_F / BK; ++kc) {
        const int buf = kc & 1;

        CP_WAIT0();
        __syncthreads();

        convert_A(smem, buf, tid);

        if (kc + 1 < IN_F / BK)
            prefetch_chunk(smb, buf ^ 1, X4, bh4, tid, rowBase, kc + 1, E);

        __syncthreads();

        const uint32_t ah_b = smb + SM_AH;
        const uint32_t bh_b = smb + SM_B + (uint32_t)buf * TILE_B;

#pragma unroll
        for (int ks = 0; ks < 2; ++ks) {
            const int kk = ks * 16;
            uint32_t af[2][4], bf[2][4];

#pragma unroll
            for (int mi = 0; mi < 2; ++mi)
                ldsm_x4(af[mi][0], af[mi][1], af[mi][2], af[mi][3],
                        ah_b + ((wm * 32 + mi * 16 + lrow) * STR + kk + lkof) * 2);
#pragma unroll
            for (int bi = 0; bi < 2; ++bi)
                ldsm_x4(bf[bi][0], bf[bi][1], bf[bi][2], bf[bi][3],
                        bh_b + ((wn * 32 + bi * 16 + lrow) * STR + kk + lkof) * 2);
#pragma unroll
            for (int mi = 0; mi < 2; ++mi)
#pragma unroll
                for (int bi = 0; bi < 2; ++bi) {
                    mma16816(acc[mi][bi * 2 + 0], af[mi][0], af[mi][1], af[mi][2], af[mi][3],
                             bf[bi][0], bf[bi][2]);
                    mma16816(acc[mi][bi * 2 + 1], af[mi][0], af[mi][1], af[mi][2], af[mi][3],
                             bf[bi][1], bf[bi][3]);
                }
        }
        __syncthreads();
    }

    // ---- epilogue: + bias, store fp16 t ----
    const int gid = lane >> 2;
    const int cid = (lane & 3) * 2;
#pragma unroll
    for (int mi = 0; mi < 2; ++mi) {
        int row0 = rowBase + wm * 32 + mi * 16 + gid;
#pragma unroll
        for (int ni = 0; ni < 4; ++ni) {
            int col = wn * 32 + ni * 8 + cid;
            float b0 = __ldg(bias + col), b1 = __ldg(bias + col + 1);
            if (row0 < E) {
                *(__half2*)(g_th + (size_t)row0 * HID + col) =
                    __floats2half2_rn(acc[mi][ni][0] + b0, acc[mi][ni][1] + b1);
            }
            if (row0 + 8 < E) {
                *(__half2*)(g_th + (size_t)(row0 + 8) * HID + col) =
                    __floats2half2_rn(acc[mi][ni][2] + b0, acc[mi][ni][3] + b1);
            }
        }
    }
}

// =====================================================================
// out[i] = t[i] + sum_k t[nbr[i][k]] : R10 gather (one warp/edge,
// uint2 lanes, HADD2 balanced tree) — best measured variant.
// =====================================================================
__global__ __launch_bounds__(256)
void gather_sum_kernel(const int* __restrict__ nbr,
                       float* __restrict__ out,
                       int E) {
    int gtid = blockIdx.x * blockDim.x + threadIdx.x;
    int e    = gtid >> 5;
    int lane = threadIdx.x & 31;
    if (e >= E) return;

    const uint2* H2 = (const uint2*)g_th;    // 2 half2 per uint2; 32 per row

    int j = 0;
    if (lane < 16) j = nbr[e * 16 + lane];

    uint2 s = H2[(size_t)e * 32 + lane];     // self

    uint2 v[16];
#pragma unroll
    for (int k = 0; k < 16; ++k) {
        int n = __shfl_sync(0xffffffffu, j, k);
        v[k] = H2[(size_t)n * 32 + lane];
    }

    __half2 tx[16], ty[16];
#pragma unroll
    for (int k = 0; k < 16; ++k) {
        tx[k] = *(const __half2*)&v[k].x;
        ty[k] = *(const __half2*)&v[k].y;
    }
#pragma unroll
    for (int stride = 8; stride >= 1; stride >>= 1)
#pragma unroll
        for (int k = 0; k < stride; ++k) {
            tx[k] = __hadd2(tx[k], tx[k + stride]);
            ty[k] = __hadd2(ty[k], ty[k + stride]);
        }

    float2 fx = __half22float2(tx[0]);
    float2 fy = __half22float2(ty[0]);
    float2 sa = __half22float2(*(const __half2*)&s.x);
    float2 sb = __half22float2(*(const __half2*)&s.y);
    float4 o;
    o.x = sa.x + fx.x;
    o.y = sa.y + fx.y;
    o.z = sb.x + fy.x;
    o.w = sb.y + fy.y;
    ((float4*)out)[(size_t)e * 32 + lane] = o;
}

extern "C" void kernel_launch(void* const* d_in, const int* in_sizes, int n_in,
                              void* d_out, int out_size) {
    const float* X   = (const float*)d_in[0];   // edge_feats [E, 256]
    const int*   nbr = (const int*)  d_in[1];   // neighbors  [E, 16]
    const float* W   = (const float*)d_in[2];   // W          [256, 128]
    const float* b   = (const float*)d_in[3];   // b          [128]
    float* out = (float*)d_out;                 // [E, 128]

    int E = in_sizes[0] / IN_F;

    cudaFuncSetAttribute(gemm_mma_kernel,
                         cudaFuncAttributeMaxDynamicSharedMemorySize, SMEM_BYTES);

    wconv_kernel<<<(IN_F * HID + 255) / 256, 256>>>(W);

    int gblocks = (E + 63) / 64;
    gemm_mma_kernel<<<gblocks, 256, SMEM_BYTES>>>(X, b, E);

    long long threads = (long long)E * 32;      // one warp per edge
    int blocks2 = (int)((threads + 255) / 256);
    gather_sum_kernel<<<blocks2, 256>>>(nbr, out, E);
}

// round 16
// speedup vs baseline: 1.0367x; 1.0367x over previous
#include <cuda_runtime.h>
#include <cuda_fp16.h>
#include <cstdint>

#define E_MAX 100096
#define IN_F  256
#define HID   128

// scratch (device globals = allowed scratch)
__device__ __half g_th[(size_t)E_MAX * HID];    // fp16 t (self + gather)
__device__ __half g_wh[HID * IN_F];             // W transposed [n][k], fp16

__device__ __forceinline__ uint32_t smem_u32(const void* p) {
    uint32_t a;
    asm("{ .reg .u64 t; cvta.to.shared.u64 t, %1; cvt.u32.u64 %0, t; }" : "=r"(a) : "l"(p));
    return a;
}
__device__ __forceinline__ void ldsm_x4(uint32_t& r0, uint32_t& r1, uint32_t& r2,
                                        uint32_t& r3, uint32_t addr) {
    asm volatile("ldmatrix.sync.aligned.m8n8.x4.shared.b16 {%0,%1,%2,%3}, [%4];"
                 : "=r"(r0), "=r"(r1), "=r"(r2), "=r"(r3) : "r"(addr));
}
__device__ __forceinline__ void mma16816(float* c, uint32_t a0, uint32_t a1,
                                         uint32_t a2, uint32_t a3,
                                         uint32_t b0, uint32_t b1) {
    asm volatile(
        "mma.sync.aligned.m16n8k16.row.col.f32.f16.f16.f32 "
        "{%0,%1,%2,%3}, {%4,%5,%6,%7}, {%8,%9}, {%0,%1,%2,%3};"
        : "+f"(c[0]), "+f"(c[1]), "+f"(c[2]), "+f"(c[3])
        : "r"(a0), "r"(a1), "r"(a2), "r"(a3), "r"(b0), "r"(b1));
}
__device__ __forceinline__ void cp_async16(uint32_t dst, const void* src) {
    asm volatile("cp.async.cg.shared.global [%0], [%1], 16;" :: "r"(dst), "l"(src));
}
#define CP_COMMIT() asm volatile("cp.async.commit_group;" ::: "memory")
#define CP_WAIT0()  asm volatile("cp.async.wait_group 0;" ::: "memory")

// =====================================================================
// W transpose -> fp16 (one-shot tiny kernel)
// =====================================================================
__global__ void wconv_kernel(const float* __restrict__ W) {
    int i = blockIdx.x * 256 + threadIdx.x;
    if (i >= IN_F * HID) return;
    int k = i >> 7, n = i & 127;
    g_wh[n * IN_F + k] = __float2half_rn(W[i]);
}

// =====================================================================
// t = Xh @ Wh + b : single-pass fp16 HMMA, fp32 accum  (R10 structure,
// A tile now double-buffered -> 2 barriers per chunk instead of 3)
// CTA = 128x128, 8 warps (4m x 2n), BK=32, cp.async double-buffered.
// =====================================================================
#define BK 32
#define STR 40                       // smem row stride (halves): 80 B
#define TILE_A (128 * STR * 2)       // 10240 B per fp16 A tile
#define TILE_B (128 * STR * 2)       // 10240 B per fp16 B tile

#define SM_XF 0                      // X fp32 staging: 2 x 16384
#define SM_AH 32768                  // A fp16 tiles: 2 x 10240 (double-buffered)
#define SM_B  53248                  // B tiles: 2 x 10240 (double-buffered)
#define SMEM_BYTES (53248 + 20480)   // 73728 -> still 2 CTAs/SM

__device__ __forceinline__ void prefetch_chunk(
    uint32_t smb, int buf,
    const float4* __restrict__ X4,
    const uint4* __restrict__ bh4,
    int tid, int rowBase, int kc, int E)
{
    uint32_t xdst = smb + SM_XF + buf * 16384;
#pragma unroll
    for (int it = 0; it < 4; ++it) {
        int i = it * 256 + tid;          // 1024 float4
        int r = i >> 3, f = i & 7;
        int grow = rowBase + r;
        if (grow >= E) grow = E - 1;
        cp_async16(xdst + i * 16, X4 + grow * (IN_F / 4) + kc * 8 + f);
    }
    uint32_t bdst = smb + SM_B + buf * TILE_B;
#pragma unroll
    for (int it = 0; it < 2; ++it) {
        int i = it * 256 + tid;          // 512 uint4
        int n = i >> 2, q = i & 3;
        uint32_t off = (uint32_t)(n * STR + q * 8) * 2;    // 16B-aligned
        cp_async16(bdst + off, bh4 + n * 32 + kc * 4 + q);
    }
    CP_COMMIT();
}

__device__ __forceinline__ void convert_A(char* smem, int buf, int tid) {
    const float4* xf = (const float4*)(smem + SM_XF + buf * 16384);
    __half* sAh = (__half*)(smem + SM_AH + buf * TILE_A);
#pragma unroll
    for (int it = 0; it < 4; ++it) {
        int i = it * 256 + tid;
        int r = i >> 3, f = i & 7;
        float4 v = xf[i];
        uint2 hp;
        hp.x = ((uint32_t)__half_as_ushort(__float2half_rn(v.y)) << 16)
             |  __half_as_ushort(__float2half_rn(v.x));
        hp.y = ((uint32_t)__half_as_ushort(__float2half_rn(v.w)) << 16)
             |  __half_as_ushort(__float2half_rn(v.z));
        *(uint2*)(sAh + r * STR + f * 4) = hp;
    }
}

__global__ __launch_bounds__(256, 2)
void gemm_mma_kernel(const float* __restrict__ X,
                     const float* __restrict__ bias,
                     int E) {
    extern __shared__ char smem[];

    const int tid  = threadIdx.x;
    const int wid  = tid >> 5;
    const int lane = tid & 31;
    const int wm   = wid & 3;
    const int wn   = wid >> 2;
    const int rowBase = blockIdx.x * 128;

    float acc[2][8][4];
#pragma unroll
    for (int mi = 0; mi < 2; ++mi)
#pragma unroll
        for (int ni = 0; ni < 8; ++ni)
#pragma unroll
            for (int q = 0; q < 4; ++q) acc[mi][ni][q] = 0.f;

    const float4* X4  = (const float4*)X;
    const uint4*  bh4 = (const uint4*)g_wh;

    const uint32_t smb = smem_u32(smem);

    const int lrow = (lane & 7) + ((lane >> 3) & 1) * 8;
    const int lkof = ((lane >> 4) & 1) * 8;

    prefetch_chunk(smb, 0, X4, bh4, tid, rowBase, 0, E);

    for (int kc = 0; kc < IN_F / BK; ++kc) {
        const int buf = kc & 1;

        CP_WAIT0();
        __syncthreads();                 // staged X/B[buf] visible; all prior compute done

        convert_A(smem, buf, tid);       // writes A[buf] (other buffer than last compute)

        if (kc + 1 < IN_F / BK)
            prefetch_chunk(smb, buf ^ 1, X4, bh4, tid, rowBase, kc + 1, E);

        __syncthreads();                 // A[buf] ready for compute

        const uint32_t ah_b = smb + SM_AH + (uint32_t)buf * TILE_A;
        const uint32_t bh_b = smb + SM_B  + (uint32_t)buf * TILE_B;

#pragma unroll
        for (int ks = 0; ks < 2; ++ks) {
            const int kk = ks * 16;
            uint32_t af[2][4], bf[4][4];

#pragma unroll
            for (int mi = 0; mi < 2; ++mi)
                ldsm_x4(af[mi][0], af[mi][1], af[mi][2], af[mi][3],
                        ah_b + ((wm * 32 + mi * 16 + lrow) * STR + kk + lkof) * 2);
#pragma unroll
            for (int bi = 0; bi < 4; ++bi)
                ldsm_x4(bf[bi][0], bf[bi][1], bf[bi][2], bf[bi][3],
                        bh_b + ((wn * 64 + bi * 16 + lrow) * STR + kk + lkof) * 2);
#pragma unroll
            for (int mi = 0; mi < 2; ++mi)
#pragma unroll
                for (int bi = 0; bi < 4; ++bi) {
                    mma16816(acc[mi][bi * 2 + 0], af[mi][0], af[mi][1], af[mi][2], af[mi][3],
                             bf[bi][0], bf[bi][2]);
                    mma16816(acc[mi][bi * 2 + 1], af[mi][0], af[mi][1], af[mi][2], af[mi][3],
                             bf[bi][1], bf[bi][3]);
                }
        }
        // no trailing barrier: next iteration's first sync orders everything
    }

    // ---- epilogue: + bias, store fp16 t ----
    const int gid = lane >> 2;
    const int cid = (lane & 3) * 2;
#pragma unroll
    for (int mi = 0; mi < 2; ++mi) {
        int row0 = rowBase + wm * 32 + mi * 16 + gid;
#pragma unroll
        for (int ni = 0; ni < 8; ++ni) {
            int col = wn * 64 + ni * 8 + cid;
            float b0 = __ldg(bias + col), b1 = __ldg(bias + col + 1);
            if (row0 < E) {
                *(__half2*)(g_th + (size_t)row0 * HID + col) =
                    __floats2half2_rn(acc[mi][ni][0] + b0, acc[mi][ni][1] + b1);
            }
            if (row0 + 8 < E) {
                *(__half2*)(g_th + (size_t)(row0 + 8) * HID + col) =
                    __floats2half2_rn(acc[mi][ni][2] + b0, acc[mi][ni][3] + b1);
            }
        }
    }
}

// =====================================================================
// out[i] = t[i] + sum_k t[nbr[i][k]] : R10 gather (one warp/edge,
// uint2 lanes, SHFL indices, HADD2 balanced tree) — best measured.
// =====================================================================
__global__ __launch_bounds__(256)
void gather_sum_kernel(const int* __restrict__ nbr,
                       float* __restrict__ out,
                       int E) {
    int gtid = blockIdx.x * blockDim.x + threadIdx.x;
    int e    = gtid >> 5;
    int lane = threadIdx.x & 31;
    if (e >= E) return;

    const uint2* H2 = (const uint2*)g_th;    // 2 half2 per uint2; 32 per row

    int j = 0;
    if (lane < 16) j = nbr[e * 16 + lane];

    uint2 s = H2[(size_t)e * 32 + lane];     // self

    uint2 v[16];
#pragma unroll
    for (int k = 0; k < 16; ++k) {
        int n = __shfl_sync(0xffffffffu, j, k);
        v[k] = H2[(size_t)n * 32 + lane];
    }

    __half2 tx[16], ty[16];
#pragma unroll
    for (int k = 0; k < 16; ++k) {
        tx[k] = *(const __half2*)&v[k].x;
        ty[k] = *(const __half2*)&v[k].y;
    }
#pragma unroll
    for (int stride = 8; stride >= 1; stride >>= 1)
#pragma unroll
        for (int k = 0; k < stride; ++k) {
            tx[k] = __hadd2(tx[k], tx[k + stride]);
            ty[k] = __hadd2(ty[k], ty[k + stride]);
        }

    float2 fx = __half22float2(tx[0]);
    float2 fy = __half22float2(ty[0]);
    float2 sa = __half22float2(*(const __half2*)&s.x);
    float2 sb = __half22float2(*(const __half2*)&s.y);
    float4 o;
    o.x = sa.x + fx.x;
    o.y = sa.y + fx.y;
    o.z = sb.x + fy.x;
    o.w = sb.y + fy.y;
    ((float4*)out)[(size_t)e * 32 + lane] = o;
}

extern "C" void kernel_launch(void* const* d_in, const int* in_sizes, int n_in,
                              void* d_out, int out_size) {
    const float* X   = (const float*)d_in[0];   // edge_feats [E, 256]
    const int*   nbr = (const int*)  d_in[1];   // neighbors  [E, 16]
    const float* W   = (const float*)d_in[2];   // W          [256, 128]
    const float* b   = (const float*)d_in[3];   // b          [128]
    float* out = (float*)d_out;                 // [E, 128]

    int E = in_sizes[0] / IN_F;

    cudaFuncSetAttribute(gemm_mma_kernel,
                         cudaFuncAttributeMaxDynamicSharedMemorySize, SMEM_BYTES);

    wconv_kernel<<<(IN_F * HID + 255) / 256, 256>>>(W);

    int gblocks = (E + 127) / 128;
    gemm_mma_kernel<<<gblocks, 256, SMEM_BYTES>>>(X, b, E);

    long long threads = (long long)E * 32;      // one warp per edge
    int blocks2 = (int)((threads + 255) / 256);
    gather_sum_kernel<<<blocks2, 256>>>(nbr, out, E);
}